// round 8
// baseline (speedup 1.0000x reference)
#include <cuda_runtime.h>
#include <cuda_bf16.h>

// Box_diamond: two-layer soft-AND over 8-wide bins.
// out[b,p] = 1/(1 - log prod_m( (s_m - W2[p,m]) / s_m )),
// s_m = 1 - log prod_{l:|l-m|<=3} (1 - x[..]*W1[p,l-m]),  p = 4g+j
// W1[p,d]=sigmoid(d*(t2-d)) <=6e-6 for |d|>=4 -> truncated window.
// R8: R7 architecture with the snapshot-offset fix (slot(l,g)=l*4+g lives at
// float offset l*16+g*4; R7 erroneously used g*16). cp.async double-buffer
// ring over 4 tiles/block, conflict-free SMEM (pitch 144), lane=(b4,sub)
// mapping -> direct coalesced stores, W1 in regs, f32x2 packed math.

#define D_TOT   4096
#define P_TOT   512
#define NTH     256
#define TILES   4
#define PITCH   144          // floats; 144 mod 32 == 16 -> conflict-free phases

typedef unsigned long long u64;

#define ONE2     0x3F8000003F800000ULL  // {1.0f, 1.0f}
#define NEGLN2_2 0xBF317218BF317218ULL  // {-ln2, -ln2}

__device__ __forceinline__ u64 fma2(u64 a, u64 b, u64 c) {
    u64 d; asm("fma.rn.f32x2 %0, %1, %2, %3;" : "=l"(d) : "l"(a), "l"(b), "l"(c)); return d;
}
__device__ __forceinline__ u64 mul2(u64 a, u64 b) {
    u64 d; asm("mul.rn.f32x2 %0, %1, %2;" : "=l"(d) : "l"(a), "l"(b)); return d;
}
__device__ __forceinline__ u64 pack2(float lo, float hi) {
    u64 d; asm("mov.b64 %0, {%1, %2};" : "=l"(d) : "f"(lo), "f"(hi)); return d;
}
__device__ __forceinline__ void unpack2(float& lo, float& hi, u64 v) {
    asm("mov.b64 {%0, %1}, %2;" : "=f"(lo), "=f"(hi) : "l"(v));
}
__device__ __forceinline__ float frcp(float v) {
    float r; asm("rcp.approx.f32 %0, %1;" : "=f"(r) : "f"(v)); return r;
}
__device__ __forceinline__ float fsigmoid(float z) {
    return frcp(1.0f + __expf(-z));
}
__device__ __forceinline__ unsigned smem_u32(const void* p) {
    return (unsigned)__cvta_generic_to_shared(p);
}
__device__ __forceinline__ void cp_async16(unsigned dst, const void* src) {
    asm volatile("cp.async.cg.shared.global [%0], [%1], 16;" :: "r"(dst), "l"(src));
}
__device__ __forceinline__ void st_stream_f2(float* p, float a, float b) {
    asm volatile("st.global.cs.v2.f32 [%0], {%1, %2};" :: "l"(p), "f"(a), "f"(b));
}

__global__ __launch_bounds__(NTH, 4)
void box_diamond_kernel(const float* __restrict__ x,
                        const float* __restrict__ t0,
                        const float* __restrict__ t1,
                        const float* __restrict__ t2,
                        float* __restrict__ out) {
    __shared__ __align__(16) float xs[2][32][PITCH];  // 36 KB double buffer
    __shared__ float w1s[7][16];   // -W1 [d+3][p_local]
    __shared__ float w2s[8][16];   // 1-W2 [m][p_local]

    const int tid   = threadIdx.x;
    const int by    = blockIdx.y;           // p-tile of 16
    const int pbase = by * 16;
    const int btile0 = blockIdx.x * TILES;  // first 32-row tile index

    // staging: 1024 16B-chunks per tile, 4 per thread.
    // GMEM chunk c (0..31) within a row covers floats [c*4, c*4+4):
    //   f = g*32 + l*4 + j  =>  c = g*8 + l  =>  g = c>>3, l = c&7
    // SMEM slot(l,g) = l*4 + g  (4 floats per slot, j-contiguous)
    const float* xbase = x + (size_t)by * 128;

    // ---- prefetch tiles 0 and 1 ----
    #pragma unroll
    for (int pre = 0; pre < 2; pre++) {
        const float* src = xbase + (size_t)(btile0 + pre) * 32 * D_TOT;
        #pragma unroll
        for (int it = 0; it < 4; it++) {
            int idx = it * NTH + tid;
            int r   = idx >> 5;
            int c   = idx & 31;
            int slot = (c & 7) * 4 + (c >> 3);      // l*4 + g
            cp_async16(smem_u32(&xs[pre][r][slot * 4]),
                       src + (size_t)r * D_TOT + c * 4);
        }
        asm volatile("cp.async.commit_group;");
    }

    // ---- build tables (overlaps copy flight) ----
    if (tid < 112) {              // -W1: 7d x 16p
        int d  = tid >> 4;
        int pl = tid & 15;
        float dd = (float)(d - 3);
        w1s[d][pl] = -fsigmoid(dd * (t2[pbase + pl] - dd));
    }
    if (tid < 128) {              // 1-W2: 8m x 16p
        int m  = tid >> 4;
        int pl = tid & 15;
        int p  = pbase + pl;
        float lf = (float)m;
        float z1 = (lf - t0[p]) * (t1[p] - lf);
        float z2 = (7.0f - t2[p] - lf) * lf;
        w2s[m][pl] = 1.0f - fsigmoid(z1) * fsigmoid(z2);
    }

    // compute-side mapping: lane = b4*8 + sub
    const int w    = tid >> 5;
    const int lane = tid & 31;
    const int b4   = lane >> 3;             // 0..3
    const int sub  = lane & 7;              // p-pair (p_local = 2*sub)
    const int row  = w * 4 + b4;            // 0..31 within tile
    const int g    = sub >> 1;
    const int jp   = sub & 1;
    const int roff = (g << 2) + (jp << 1);  // float offset within slot row: g*4 + jp*2

    u64 w1r[7];
    bool w1_loaded = false;
    const float LN2 = 0.6931471805599453f;

    #pragma unroll
    for (int t = 0; t < TILES; t++) {
        asm volatile("cp.async.wait_group 1;");
        __syncthreads();                     // xs[t&1] ready (+tables on t=0)

        if (!w1_loaded) {                    // broadcast LDS after first barrier
            #pragma unroll
            for (int d = 0; d < 7; d++)
                w1r[d] = *reinterpret_cast<const u64*>(&w1s[d][sub * 2]);
            w1_loaded = true;
        }

        // ---- snapshot x: 8 conflict-free LDS.64 ----
        // float offset of (l, g, jp) = slot(l,g)*4 + jp*2 = l*16 + g*4 + jp*2
        u64 nx[8];
        #pragma unroll
        for (int l = 0; l < 8; l++)
            nx[l] = *reinterpret_cast<const u64*>(&xs[t & 1][row][l * 16 + roff]);
        __syncthreads();                     // xs[t&1] free for reuse

        // ---- prefetch tile t+2 into the freed buffer ----
        if (t + 2 < TILES) {
            const float* src = xbase + (size_t)(btile0 + t + 2) * 32 * D_TOT;
            #pragma unroll
            for (int it = 0; it < 4; it++) {
                int idx = it * NTH + tid;
                int r   = idx >> 5;
                int c   = idx & 31;
                int slot = (c & 7) * 4 + (c >> 3);
                cp_async16(smem_u32(&xs[t & 1][r][slot * 4]),
                           src + (size_t)r * D_TOT + c * 4);
            }
        }
        asm volatile("cp.async.commit_group;");

        // ---- compute: 8 m, truncated l-window ----
        u64 num = ONE2, den = ONE2;
        #pragma unroll
        for (int m = 0; m < 8; m++) {
            const int lo = (m - 3 < 0) ? 0 : m - 3;
            const int hi = (m + 3 > 7) ? 7 : m + 3;
            u64 pr = fma2(nx[lo], w1r[lo - m + 3], ONE2);   // 1 - x*W1
            #pragma unroll
            for (int l = lo + 1; l <= hi; l++)
                pr = mul2(pr, fma2(nx[l], w1r[l - m + 3], ONE2));
            float a0, a1;
            unpack2(a0, a1, pr);
            u64 lg  = pack2(__log2f(a0), __log2f(a1));
            u64 w2v = *reinterpret_cast<const u64*>(&w2s[m][sub * 2]);
            num = mul2(num, fma2(lg, NEGLN2_2, w2v));   // s - W2
            den = mul2(den, fma2(lg, NEGLN2_2, ONE2));  // s
        }

        float n0, n1, d0, d1;
        unpack2(n0, n1, num);
        unpack2(d0, d1, den);
        float o0 = frcp(fmaf(-LN2, __log2f(n0) - __log2f(d0), 1.0f));
        float o1 = frcp(fmaf(-LN2, __log2f(n1) - __log2f(d1), 1.0f));

        // ---- direct coalesced store (64B per b-row) ----
        int brow = (btile0 + t) * 32 + row;
        st_stream_f2(out + (size_t)brow * P_TOT + pbase + sub * 2, o0, o1);
    }
}

extern "C" void kernel_launch(void* const* d_in, const int* in_sizes, int n_in,
                              void* d_out, int out_size) {
    const float* x  = (const float*)d_in[0];
    const float* t0 = (const float*)d_in[1];
    const float* t1 = (const float*)d_in[2];
    const float* t2 = (const float*)d_in[3];
    float* out = (float*)d_out;

    int B = in_sizes[0] / D_TOT;                    // 4096
    dim3 grid(B / (32 * TILES), P_TOT / 16);        // (32, 32) = 1024 blocks
    box_diamond_kernel<<<grid, NTH>>>(x, t0, t1, t2, out);
}